// round 1
// baseline (speedup 1.0000x reference)
#include <cuda_runtime.h>

// out[i, :] = sum_k ppr_scores[i,k] * x[ppr_idx[i,k], :]
// N=100000 rows, K=32 neighbors, D=128 features (fp32).
//
// Layout: one warp per output row. Each lane owns one (idx, score) pair
// (K==32==warpSize), broadcast per-iteration via shfl. The warp streams
// neighbor rows as coalesced float4 loads (512B per row == 4 L2 sectors).
// x (51.2 MB) fits in L2, so the 1.64 GB gather is L2-bandwidth bound.

#define KNEIGH 32
#define DVEC   32   // D/4 float4 per row

__global__ __launch_bounds__(256) void ppr_gather_kernel(
    const float4* __restrict__ x,      // [N, 32] float4
    const int*    __restrict__ idx,    // [N, 32]
    const float*  __restrict__ sc,     // [N, 32]
    float4*       __restrict__ out,    // [N, 32] float4
    int n)
{
    const int warp = (blockIdx.x * blockDim.x + threadIdx.x) >> 5;
    const int lane = threadIdx.x & 31;
    if (warp >= n) return;

    // Each lane holds neighbor index/score for k == lane.
    const int   my_j = idx[warp * KNEIGH + lane];
    const float my_s = sc[warp * KNEIGH + lane];

    float4 acc = make_float4(0.f, 0.f, 0.f, 0.f);

    #pragma unroll
    for (int k = 0; k < KNEIGH; k += 8) {
        // Batch 8 independent row loads per group for MLP to hide L2 latency.
        float4 v[8];
        float  s[8];
        #pragma unroll
        for (int u = 0; u < 8; ++u) {
            int   jk = __shfl_sync(0xffffffffu, my_j, k + u);
            s[u]     = __shfl_sync(0xffffffffu, my_s, k + u);
            v[u]     = x[(long long)jk * DVEC + lane];
        }
        #pragma unroll
        for (int u = 0; u < 8; ++u) {
            acc.x += s[u] * v[u].x;
            acc.y += s[u] * v[u].y;
            acc.z += s[u] * v[u].z;
            acc.w += s[u] * v[u].w;
        }
    }

    out[warp * DVEC + lane] = acc;
}

extern "C" void kernel_launch(void* const* d_in, const int* in_sizes, int n_in,
                              void* d_out, int out_size)
{
    const float4* x   = (const float4*)d_in[0];   // [N, D] fp32
    const int*    idx = (const int*)d_in[1];      // [N, K] int32
    const float*  sc  = (const float*)d_in[2];    // [N, K] fp32
    float4*       out = (float4*)d_out;           // [N, D] fp32

    const int n = in_sizes[1] / KNEIGH;           // N rows

    const int warps_per_block = 8;                // 256 threads
    const int blocks = (n + warps_per_block - 1) / warps_per_block;
    ppr_gather_kernel<<<blocks, warps_per_block * 32>>>(x, idx, sc, out, n);
}